// round 15
// baseline (speedup 1.0000x reference)
#include <cuda_runtime.h>
#include <cuda_fp16.h>
#include <math.h>

#define BB 2
#define CC 256
#define NQ 4096

// ---------------- scratch ----------------
__device__ float  g_Q  [BB*NQ*CC];
__device__ __half g_V0h[BB*4096*CC];
__device__ __half g_V1h[BB*1024*CC];
__device__ __half g_V2h[BB*256*CC];
__device__ float  g_OFW[BB*NQ*144];
__device__ float  g_OW [144*CC];
__device__ float  g_OWb[144];
__device__ __half g_ACCh[(size_t)BB*NQ*1024];
__device__ float  g_Y  [BB*NQ*CC];
__device__ float  g_Z  [BB*NQ*CC];
__device__ __half g_Zh [BB*NQ*CC];
__device__ __half g_Hh [(size_t)BB*NQ*1024];
__device__ __half g_OutWh[256*1024];
__device__ __half g_F1Wh [1024*256];
__device__ __half g_F2Wh [256*1024];

#define BM 128
#define BN 64

// ---------------- helpers ----------------
__device__ __forceinline__ void mma16(float d[4],
                                      unsigned a0, unsigned a1, unsigned a2, unsigned a3,
                                      unsigned b0, unsigned b1)
{
    asm volatile(
        "mma.sync.aligned.m16n8k16.row.col.f32.f16.f16.f32 "
        "{%0,%1,%2,%3},{%4,%5,%6,%7},{%8,%9},{%0,%1,%2,%3};"
        : "+f"(d[0]), "+f"(d[1]), "+f"(d[2]), "+f"(d[3])
        : "r"(a0), "r"(a1), "r"(a2), "r"(a3), "r"(b0), "r"(b1));
}

__device__ __forceinline__ void ldsm_x4(unsigned& r0, unsigned& r1, unsigned& r2, unsigned& r3,
                                        unsigned addr)
{
    asm volatile("ldmatrix.sync.aligned.m8n8.x4.shared.b16 {%0,%1,%2,%3},[%4];"
                 : "=r"(r0), "=r"(r1), "=r"(r2), "=r"(r3) : "r"(addr));
}

__device__ __forceinline__ void ldsm_x4_t(unsigned& r0, unsigned& r1, unsigned& r2, unsigned& r3,
                                          unsigned addr)
{
    asm volatile("ldmatrix.sync.aligned.m8n8.x4.trans.shared.b16 {%0,%1,%2,%3},[%4];"
                 : "=r"(r0), "=r"(r1), "=r"(r2), "=r"(r3) : "r"(addr));
}

__device__ __forceinline__ unsigned h2u(__half2 h) { return *(unsigned*)&h; }

__device__ __forceinline__ float gelu_exact(float v)
{
    return 0.5f * v * (1.f + erff(v * 0.70710678118654752f));
}

__device__ __forceinline__ void fma_f32x2(unsigned long long& acc,
                                          unsigned long long v, unsigned long long w)
{
    asm("fma.rn.f32x2 %0, %1, %2, %0;" : "+l"(acc) : "l"(v), "l"(w));
}
__device__ __forceinline__ unsigned long long pack2(float lo, float hi)
{
    unsigned long long r;
    asm("mov.b64 %0, {%1, %2};" : "=l"(r) : "f"(lo), "f"(hi));
    return r;
}
__device__ __forceinline__ float2 unpack2(unsigned long long v)
{
    float2 r;
    asm("mov.b64 {%0, %1}, %2;" : "=f"(r.x), "=f"(r.y) : "l"(v));
    return r;
}
__device__ __forceinline__ unsigned long long h2_to_f2u(unsigned h2raw)
{
    __half2 h = *(__half2*)&h2raw;
    float2 f = __half22float2(h);
    return pack2(f.x, f.y);
}

#define CPA16(dst, src) asm volatile("cp.async.cg.shared.global [%0], [%1], 16;" :: "r"(dst), "l"(src))

// =====================================================================
// gemm_hh: pure-fp16 GEMM, 3-stage cp.async pipeline (dynamic smem).
// =====================================================================
#define BNH 128
#define HH_STAGE_BYTES 10240
#define HH_SMEM (3 * 2 * HH_STAGE_BYTES)

__global__ void __launch_bounds__(256, 2) gemm_hh(
    const __half* __restrict__ A, long long sab,
    const __half* __restrict__ W,
    const float* __restrict__ bias,
    const float* __restrict__ R, long long srb, long long srm, long long srn,
    float* __restrict__ Cout, long long scb, long long scm, long long scn,
    int M, int N, int K, int act, int half_out)
{
    extern __shared__ __align__(16) __half sm_hh[];
    __half* Ahs = sm_hh;
    __half* Bhs = sm_hh + 3 * 5120;

    const int tid = threadIdx.x;
    const int lane = tid & 31, warp = tid >> 5;
    const int g = lane >> 2, tg = lane & 3;
    const int wm = (warp >> 2) * 64, wn = (warp & 3) * 32;
    const int m0 = blockIdx.y * BM, n0 = blockIdx.x * BNH;

    A += (long long)blockIdx.z * sab;
    if (R) R += (long long)blockIdx.z * srb;
    float* CoutF = Cout + (long long)blockIdx.z * scb;
    __half* CoutH = (__half*)Cout + (long long)blockIdx.z * scb;

    const unsigned aS = (unsigned)__cvta_generic_to_shared(Ahs);
    const unsigned bS = (unsigned)__cvta_generic_to_shared(Bhs);

    const int r0 = tid >> 2, c0 = tid & 3;
    const int r1 = r0 + 64;
    const unsigned dA0 = (unsigned)((r0 * 40 + c0 * 8) * 2);
    const unsigned dA1 = (unsigned)((r1 * 40 + c0 * 8) * 2);

#define LOADHH(stg, k0_)                                                                   \
    {                                                                                      \
        CPA16(aS + (stg) * HH_STAGE_BYTES + dA0, A + (long long)(m0 + r0) * K + (k0_) + c0 * 8); \
        CPA16(aS + (stg) * HH_STAGE_BYTES + dA1, A + (long long)(m0 + r1) * K + (k0_) + c0 * 8); \
        CPA16(bS + (stg) * HH_STAGE_BYTES + dA0, W + (long long)(n0 + r0) * K + (k0_) + c0 * 8); \
        CPA16(bS + (stg) * HH_STAGE_BYTES + dA1, W + (long long)(n0 + r1) * K + (k0_) + c0 * 8); \
        asm volatile("cp.async.commit_group;");                                            \
    }

    const unsigned offA  = (unsigned)(((wm + (lane & 7) + 8 * ((lane >> 3) & 1)) * 40 + 8 * (lane >> 4)) * 2);
    const unsigned offB0 = (unsigned)(((wn + (lane & 7) + 8 * (lane >> 4)) * 40 + 8 * ((lane >> 3) & 1)) * 2);
    const unsigned offB1 = (unsigned)(((wn + 16 + (lane & 7) + 8 * (lane >> 4)) * 40 + 8 * ((lane >> 3) & 1)) * 2);

    const int nk = K / 32;
    LOADHH(0, 0);
    LOADHH(1, 32);

    float acc[4][4][4] = {};

    for (int t = 0; t < nk; t++) {
        const int s = t % 3;
        if (t + 1 < nk) asm volatile("cp.async.wait_group 1;");
        else            asm volatile("cp.async.wait_group 0;");
        __syncthreads();

        #pragma unroll
        for (int ks = 0; ks < 2; ks++) {
            unsigned q0, q1, q2, q3, q4, q5, q6, q7;
            ldsm_x4(q0, q1, q2, q3, bS + s * HH_STAGE_BYTES + offB0 + ks * 32);
            ldsm_x4(q4, q5, q6, q7, bS + s * HH_STAGE_BYTES + offB1 + ks * 32);
            #pragma unroll
            for (int mt = 0; mt < 4; mt++) {
                unsigned f0, f1, f2, f3;
                ldsm_x4(f0, f1, f2, f3, aS + s * HH_STAGE_BYTES + offA + mt * 1280 + ks * 32);
                mma16(acc[mt][0], f0, f1, f2, f3, q0, q1);
                mma16(acc[mt][1], f0, f1, f2, f3, q2, q3);
                mma16(acc[mt][2], f0, f1, f2, f3, q4, q5);
                mma16(acc[mt][3], f0, f1, f2, f3, q6, q7);
            }
        }
        if (t + 2 < nk) { LOADHH((t + 2) % 3, (t + 2) * 32); }
    }
#undef LOADHH

    #pragma unroll
    for (int mt = 0; mt < 4; mt++) {
        int gm0 = m0 + wm + 16 * mt + g;
        #pragma unroll
        for (int nt = 0; nt < 4; nt++) {
            int gn0 = n0 + wn + 8 * nt + 2 * tg;
            float v0 = acc[mt][nt][0], v1 = acc[mt][nt][1];
            float v2 = acc[mt][nt][2], v3 = acc[mt][nt][3];
            if (bias) {
                float b0 = bias[gn0], b1 = bias[gn0 + 1];
                v0 += b0; v1 += b1; v2 += b0; v3 += b1;
            }
            if (act) {
                v0 = gelu_exact(v0); v1 = gelu_exact(v1);
                v2 = gelu_exact(v2); v3 = gelu_exact(v3);
            }
            if (R) {
                v0 += R[(long long)gm0 * srm + (long long)gn0 * srn];
                v1 += R[(long long)gm0 * srm + (long long)(gn0 + 1) * srn];
                v2 += R[(long long)(gm0 + 8) * srm + (long long)gn0 * srn];
                v3 += R[(long long)(gm0 + 8) * srm + (long long)(gn0 + 1) * srn];
            }
            if (half_out) {
                *(__half2*)(CoutH + (long long)gm0 * scm + gn0)       = __floats2half2_rn(v0, v1);
                *(__half2*)(CoutH + (long long)(gm0 + 8) * scm + gn0) = __floats2half2_rn(v2, v3);
            } else if (scn == 1) {
                *(float2*)(CoutF + (long long)gm0 * scm + gn0)       = make_float2(v0, v1);
                *(float2*)(CoutF + (long long)(gm0 + 8) * scm + gn0) = make_float2(v2, v3);
            } else {
                CoutF[(long long)gm0 * scm + (long long)gn0 * scn]             = v0;
                CoutF[(long long)gm0 * scm + (long long)(gn0 + 1) * scn]       = v1;
                CoutF[(long long)(gm0 + 8) * scm + (long long)gn0 * scn]       = v2;
                CoutF[(long long)(gm0 + 8) * scm + (long long)(gn0 + 1) * scn] = v3;
            }
        }
    }
}

// =====================================================================
// gemm_hc: fp16 TC GEMM with fp32 inputs (V projections only).
// =====================================================================
__global__ void __launch_bounds__(256, 2) gemm_hc(
    const float* __restrict__ A, long long sab, long long sam, long long sak,
    const float* __restrict__ W,
    const float* __restrict__ bias,
    float* __restrict__ Cout, long long scb, long long scm, long long scn,
    int M, int N, int K, int half_out)
{
    __shared__ __align__(16) __half As[2][5120];
    __shared__ __align__(16) __half Bs[2][2560];

    const int tid = threadIdx.x;
    const int lane = tid & 31, warp = tid >> 5;
    const int g = lane >> 2, tg = lane & 3;
    const int wm = (warp >> 2) * 64, wn = (warp & 3) * 16;
    const int m0 = blockIdx.y * BM, n0 = blockIdx.x * BN;
    const bool kc = (sak == 1);

    A += (long long)blockIdx.z * sab;
    float* CoutF = Cout + (long long)blockIdx.z * scb;
    __half* CoutH = (__half*)Cout + (long long)blockIdx.z * scb;

    const unsigned aBase = (unsigned)__cvta_generic_to_shared(&As[0][0]);
    const unsigned bBase = (unsigned)__cvta_generic_to_shared(&Bs[0][0]);

    unsigned offA;
    if (kc) offA = (unsigned)(((wm + (lane & 7) + 8 * ((lane >> 3) & 1)) * 40 + 8 * (lane >> 4)) * 2);
    else    offA = (unsigned)((((lane & 7) + 8 * ((lane >> 4) & 1)) * 136 + wm + 8 * ((lane >> 3) & 1)) * 2);
    const unsigned offB = (unsigned)(((wn + (lane & 7) + 8 * (lane >> 4)) * 40 + 8 * ((lane >> 3) & 1)) * 2);

    float4 a0_, a1_, a2_, a3_, b0_, b1_;

#define GLOAD(k0_)                                                                          \
    if (kc) {                                                                               \
        const float* p = A + (long long)(m0 + (tid >> 1)) * sam + (k0_) + (tid & 1) * 16;   \
        a0_ = *(const float4*)p;        a1_ = *(const float4*)(p + 4);                      \
        a2_ = *(const float4*)(p + 8);  a3_ = *(const float4*)(p + 12);                     \
    } else {                                                                                \
        const float* p = A + (long long)((k0_) + (tid >> 3)) * sak + m0 + (tid & 7) * 16;   \
        a0_ = *(const float4*)p;        a1_ = *(const float4*)(p + 4);                      \
        a2_ = *(const float4*)(p + 8);  a3_ = *(const float4*)(p + 12);                     \
    }                                                                                       \
    {                                                                                       \
        const float* p = W + (long long)(n0 + (tid >> 2)) * K + (k0_) + (tid & 3) * 8;      \
        b0_ = *(const float4*)p;        b1_ = *(const float4*)(p + 4);                      \
    }

#define SSTORE(buf)                                                                         \
    {                                                                                       \
        uint4 v0, v1;                                                                       \
        v0.x = h2u(__floats2half2_rn(a0_.x, a0_.y)); v0.y = h2u(__floats2half2_rn(a0_.z, a0_.w)); \
        v0.z = h2u(__floats2half2_rn(a1_.x, a1_.y)); v0.w = h2u(__floats2half2_rn(a1_.z, a1_.w)); \
        v1.x = h2u(__floats2half2_rn(a2_.x, a2_.y)); v1.y = h2u(__floats2half2_rn(a2_.z, a2_.w)); \
        v1.z = h2u(__floats2half2_rn(a3_.x, a3_.y)); v1.w = h2u(__floats2half2_rn(a3_.z, a3_.w)); \
        __half* d;                                                                          \
        if (kc) d = &As[buf][(tid >> 1) * 40 + (tid & 1) * 16];                             \
        else    d = &As[buf][(tid >> 3) * 136 + (tid & 7) * 16];                            \
        *(uint4*)d = v0; *(uint4*)(d + 8) = v1;                                             \
        uint4 vb;                                                                           \
        vb.x = h2u(__floats2half2_rn(b0_.x, b0_.y)); vb.y = h2u(__floats2half2_rn(b0_.z, b0_.w)); \
        vb.z = h2u(__floats2half2_rn(b1_.x, b1_.y)); vb.w = h2u(__floats2half2_rn(b1_.z, b1_.w)); \
        *(uint4*)&Bs[buf][(tid >> 2) * 40 + (tid & 3) * 8] = vb;                            \
    }

    GLOAD(0); SSTORE(0);
    __syncthreads();

    float acc[4][2][4] = {};
    const int nk = K / 32;

    for (int t = 0; t < nk; t++) {
        const int buf = t & 1;
        const bool more = (t + 1 < nk);
        if (more) { GLOAD((t + 1) * 32); }

        #pragma unroll
        for (int ks = 0; ks < 2; ks++) {
            unsigned q0, q1, q2, q3;
            ldsm_x4(q0, q1, q2, q3, bBase + buf * 5120 + offB + ks * 32);
            #pragma unroll
            for (int mt = 0; mt < 4; mt++) {
                unsigned f0, f1, f2, f3;
                if (kc) ldsm_x4  (f0, f1, f2, f3, aBase + buf * 10240 + offA + mt * 1280 + ks * 32);
                else    ldsm_x4_t(f0, f1, f2, f3, aBase + buf * 10240 + offA + mt * 32 + ks * 4352);
                mma16(acc[mt][0], f0, f1, f2, f3, q0, q1);
                mma16(acc[mt][1], f0, f1, f2, f3, q2, q3);
            }
        }
        if (more) { SSTORE(buf ^ 1); }
        __syncthreads();
    }
#undef GLOAD
#undef SSTORE

    #pragma unroll
    for (int mt = 0; mt < 4; mt++) {
        int gm0 = m0 + wm + 16 * mt + g;
        #pragma unroll
        for (int nt = 0; nt < 2; nt++) {
            int gn0 = n0 + wn + 8 * nt + 2 * tg;
            float v0 = acc[mt][nt][0], v1 = acc[mt][nt][1];
            float v2 = acc[mt][nt][2], v3 = acc[mt][nt][3];
            if (bias) {
                float b0 = bias[gn0], b1 = bias[gn0 + 1];
                v0 += b0; v1 += b1; v2 += b0; v3 += b1;
            }
            if (half_out) {
                *(__half2*)(CoutH + (long long)gm0 * scm + gn0)       = __floats2half2_rn(v0, v1);
                *(__half2*)(CoutH + (long long)(gm0 + 8) * scm + gn0) = __floats2half2_rn(v2, v3);
            } else {
                *(float2*)(CoutF + (long long)gm0 * scm + gn0)       = make_float2(v0, v1);
                *(float2*)(CoutF + (long long)(gm0 + 8) * scm + gn0) = make_float2(v2, v3);
            }
        }
    }
}

// =====================================================================
// gemm_hc3: 3xFP16 hi/lo-split precise GEMM.
// =====================================================================
__global__ void __launch_bounds__(256, 2) gemm_hc3(
    const float* __restrict__ A, long long sab, long long sam, long long sak,
    const float* __restrict__ W,
    const float* __restrict__ bias,
    float* __restrict__ Cout, long long scb, long long scm,
    int M, int N, int K)
{
    __shared__ __align__(16) __half Ahs[2][3072];
    __shared__ __align__(16) __half Als[2][3072];
    __shared__ __align__(16) __half Bhs[2][1536];
    __shared__ __align__(16) __half Bls[2][1536];

    const int tid = threadIdx.x;
    const int lane = tid & 31, warp = tid >> 5;
    const int g = lane >> 2, tg = lane & 3;
    const int wm = (warp >> 2) * 64, wn = (warp & 3) * 16;
    const int m0 = blockIdx.y * BM, n0 = blockIdx.x * BN;
    const bool kc = (sak == 1);

    A    += (long long)blockIdx.z * sab;
    Cout += (long long)blockIdx.z * scb;

    const unsigned ahB = (unsigned)__cvta_generic_to_shared(&Ahs[0][0]);
    const unsigned alB = (unsigned)__cvta_generic_to_shared(&Als[0][0]);
    const unsigned bhB = (unsigned)__cvta_generic_to_shared(&Bhs[0][0]);
    const unsigned blB = (unsigned)__cvta_generic_to_shared(&Bls[0][0]);

    unsigned offA;
    if (kc) offA = (unsigned)(((wm + (lane & 15)) * 24 + 8 * (lane >> 4)) * 2);
    else    offA = (unsigned)((((lane & 7) + 8 * ((lane >> 4) & 1)) * 136 + wm + 8 * ((lane >> 3) & 1)) * 2);
    const unsigned offB = (unsigned)(((wn + (lane & 7) + 8 * (lane >> 4)) * 24 + 8 * ((lane >> 3) & 1)) * 2);

    float4 rA0, rA1, rB;

#define GLOAD3(k0_)                                                                         \
    if (kc) {                                                                               \
        const float* p = A + (long long)(m0 + (tid >> 1)) * sam + (k0_) + (tid & 1) * 8;    \
        rA0 = *(const float4*)p;  rA1 = *(const float4*)(p + 4);                            \
    } else {                                                                                \
        const float* p = A + (long long)((k0_) + (tid >> 4)) * sak + m0 + (tid & 15) * 8;   \
        rA0 = *(const float4*)p;  rA1 = *(const float4*)(p + 4);                            \
    }                                                                                       \
    {   int gn_ = n0 + (tid >> 2);                                                          \
        rB = (gn_ < N) ? *(const float4*)(W + (long long)gn_ * K + (k0_) + (tid & 3) * 4)   \
                       : make_float4(0.f, 0.f, 0.f, 0.f); }

#define SPL(x, h_, l_) { h_ = __float2half_rn(x); l_ = __float2half_rn((x) - __half2float(h_)); }

#define SSTORE3(buf)                                                                        \
    {                                                                                       \
        __half h0,h1,h2,h3,h4,h5,h6,h7, l0,l1,l2,l3,l4,l5,l6,l7;                            \
        SPL(rA0.x,h0,l0); SPL(rA0.y,h1,l1); SPL(rA0.z,h2,l2); SPL(rA0.w,h3,l3);             \
        SPL(rA1.x,h4,l4); SPL(rA1.y,h5,l5); SPL(rA1.z,h6,l6); SPL(rA1.w,h7,l7);             \
        unsigned dof;                                                                       \
        if (kc) dof = (tid >> 1) * 24 + (tid & 1) * 8;                                      \
        else    dof = (tid >> 4) * 136 + (tid & 15) * 8;                                    \
        uint4 vh, vl;                                                                       \
        vh.x = h2u(__halves2half2(h0,h1)); vh.y = h2u(__halves2half2(h2,h3));               \
        vh.z = h2u(__halves2half2(h4,h5)); vh.w = h2u(__halves2half2(h6,h7));               \
        vl.x = h2u(__halves2half2(l0,l1)); vl.y = h2u(__halves2half2(l2,l3));               \
        vl.z = h2u(__halves2half2(l4,l5)); vl.w = h2u(__halves2half2(l6,l7));               \
        *(uint4*)&Ahs[buf][dof] = vh;  *(uint4*)&Als[buf][dof] = vl;                        \
        __half bh0,bh1,bh2,bh3, bl0,bl1,bl2,bl3;                                            \
        SPL(rB.x,bh0,bl0); SPL(rB.y,bh1,bl1); SPL(rB.z,bh2,bl2); SPL(rB.w,bh3,bl3);         \
        unsigned bof = (tid >> 2) * 24 + (tid & 3) * 4;                                     \
        uint2 wh, wl;                                                                       \
        wh.x = h2u(__halves2half2(bh0,bh1)); wh.y = h2u(__halves2half2(bh2,bh3));           \
        wl.x = h2u(__halves2half2(bl0,bl1)); wl.y = h2u(__halves2half2(bl2,bl3));           \
        *(uint2*)&Bhs[buf][bof] = wh;  *(uint2*)&Bls[buf][bof] = wl;                        \
    }

    GLOAD3(0); SSTORE3(0);
    __syncthreads();

    float acc[4][2][4] = {};
    const int nk = K / 16;

    for (int t = 0; t < nk; t++) {
        const int buf = t & 1;
        const bool more = (t + 1 < nk);
        if (more) { GLOAD3((t + 1) * 16); }

        unsigned qh0, qh1, qh2, qh3, ql0, ql1, ql2, ql3;
        ldsm_x4(qh0, qh1, qh2, qh3, bhB + buf * 3072 + offB);
        ldsm_x4(ql0, ql1, ql2, ql3, blB + buf * 3072 + offB);

        #pragma unroll
        for (int mt = 0; mt < 4; mt++) {
            unsigned fh0, fh1, fh2, fh3, fl0, fl1, fl2, fl3;
            if (kc) {
                ldsm_x4  (fh0, fh1, fh2, fh3, ahB + buf * 6144 + offA + mt * 768);
                ldsm_x4  (fl0, fl1, fl2, fl3, alB + buf * 6144 + offA + mt * 768);
            } else {
                ldsm_x4_t(fh0, fh1, fh2, fh3, ahB + buf * 6144 + offA + mt * 32);
                ldsm_x4_t(fl0, fl1, fl2, fl3, alB + buf * 6144 + offA + mt * 32);
            }
            mma16(acc[mt][0], fl0, fl1, fl2, fl3, qh0, qh1);
            mma16(acc[mt][0], fh0, fh1, fh2, fh3, ql0, ql1);
            mma16(acc[mt][0], fh0, fh1, fh2, fh3, qh0, qh1);
            mma16(acc[mt][1], fl0, fl1, fl2, fl3, qh2, qh3);
            mma16(acc[mt][1], fh0, fh1, fh2, fh3, ql2, ql3);
            mma16(acc[mt][1], fh0, fh1, fh2, fh3, qh2, qh3);
        }
        if (more) { SSTORE3(buf ^ 1); }
        __syncthreads();
    }
#undef GLOAD3
#undef SSTORE3
#undef SPL

    #pragma unroll
    for (int mt = 0; mt < 4; mt++) {
        int gm0 = m0 + wm + 16 * mt + g;
        #pragma unroll
        for (int nt = 0; nt < 2; nt++) {
            int gn0 = n0 + wn + 8 * nt + 2 * tg;
            if (gn0 >= N) continue;
            float v0 = acc[mt][nt][0], v1 = acc[mt][nt][1];
            float v2 = acc[mt][nt][2], v3 = acc[mt][nt][3];
            if (bias) {
                float b0 = bias[gn0], b1 = bias[gn0 + 1];
                v0 += b0; v1 += b1; v2 += b0; v3 += b1;
            }
            *(float2*)(Cout + (long long)gm0 * scm + gn0)       = make_float2(v0, v1);
            *(float2*)(Cout + (long long)(gm0 + 8) * scm + gn0) = make_float2(v2, v3);
        }
    }
}

// ---------------- warp-per-row LN ----------------
__global__ void ln_kernel(float* __restrict__ X,
                          const float* __restrict__ g, const float* __restrict__ b)
{
    long long row = (long long)blockIdx.x * 8 + (threadIdx.x >> 5);
    int lane = threadIdx.x & 31;
    float* xr = X + row * CC;

    float v[8];
    float s = 0.f;
    #pragma unroll
    for (int j = 0; j < 8; j++) { v[j] = xr[lane + 32 * j]; s += v[j]; }
    #pragma unroll
    for (int o = 16; o; o >>= 1) s += __shfl_xor_sync(0xffffffffu, s, o);
    float mu = s * (1.f / CC);
    float s2 = 0.f;
    #pragma unroll
    for (int j = 0; j < 8; j++) { v[j] -= mu; s2 += v[j] * v[j]; }
    #pragma unroll
    for (int o = 16; o; o >>= 1) s2 += __shfl_xor_sync(0xffffffffu, s2, o);
    float r = rsqrtf(s2 * (1.f / CC) + 1e-5f);
    #pragma unroll
    for (int j = 0; j < 8; j++)
        xr[lane + 32 * j] = v[j] * r * g[lane + 32 * j] + b[lane + 32 * j];
}

// ---------------- add+LN (per-batch), writes Z fp32 + Zh fp16 ----------------
__global__ void __launch_bounds__(256) add_ln_kernel(
    const float* __restrict__ S, const float* __restrict__ Y,
    float* __restrict__ Z, __half* __restrict__ Zh,
    const float* __restrict__ g, const float* __restrict__ b_, int bb)
{
    __shared__ float Sv[CC][33];

    long long nq0 = (long long)blockIdx.x * 32;
    int tid = threadIdx.x;

    const float* Sb = S + (long long)bb * CC * NQ + nq0;
    for (int i = tid; i < CC * 32; i += 256) {
        int c = i >> 5, qi = i & 31;
        Sv[c][qi] = Sb[(long long)c * NQ + qi];
    }
    __syncthreads();

    int lane = tid & 31, warp = tid >> 5;
    #pragma unroll
    for (int it = 0; it < 4; it++) {
        int qi = warp + it * 8;
        long long row = ((long long)bb * NQ + nq0 + qi);
        const float* yr = Y + row * CC;
        float v[8];
        float s = 0.f;
        #pragma unroll
        for (int j = 0; j < 8; j++) {
            int c = lane + 32 * j;
            v[j] = Sv[c][qi] + yr[c];
            s += v[j];
        }
        #pragma unroll
        for (int o = 16; o; o >>= 1) s += __shfl_xor_sync(0xffffffffu, s, o);
        float mu = s * (1.f / CC);
        float s2 = 0.f;
        #pragma unroll
        for (int j = 0; j < 8; j++) { v[j] -= mu; s2 += v[j] * v[j]; }
        #pragma unroll
        for (int o = 16; o; o >>= 1) s2 += __shfl_xor_sync(0xffffffffu, s2, o);
        float r = rsqrtf(s2 * (1.f / CC) + 1e-5f);
        float* zr = Z + row * CC;
        __half* zh = Zh + row * CC;
        #pragma unroll
        for (int j = 0; j < 8; j++) {
            int c = lane + 32 * j;
            float zv = v[j] * r * g[c] + b_[c];
            zr[c] = zv;
            zh[c] = __float2half_rn(zv);
        }
    }
}

// ---------------- weight pack + fp16 weight conversion ----------------
__global__ void pack_kernel(const float* __restrict__ off_w, const float* __restrict__ wgt_w,
                            const float* __restrict__ off_b, const float* __restrict__ wgt_b,
                            float* __restrict__ OW, float* __restrict__ OWb)
{
    int i = blockIdx.x * 256 + threadIdx.x;
    if (i < 96 * CC) OW[i] = off_w[i];
    else if (i < 144 * CC) OW[i] = wgt_w[i - 96 * CC];
    else if (i < 144 * CC + 96) OWb[i - 144 * CC] = off_b[i - 144 * CC];
    else if (i < 144 * CC + 144) OWb[i - 144 * CC] = wgt_b[i - 144 * CC - 96];
}

__global__ void w2h_kernel(const float* __restrict__ a, const float* __restrict__ b,
                           const float* __restrict__ c,
                           __half* __restrict__ ah, __half* __restrict__ bh,
                           __half* __restrict__ ch)
{
    int i = blockIdx.x * 256 + threadIdx.x;
    if (i < 256 * 1024) {
        ah[i] = __float2half_rn(a[i]);
        bh[i] = __float2half_rn(b[i]);
        ch[i] = __float2half_rn(c[i]);
    }
}

// ---------------- fused softmax + sampling (per-half, qbase) ----------------
__global__ void __launch_bounds__(256) sample_kernel(
    const float* __restrict__ OFW, const float* __restrict__ sim,
    const __half* __restrict__ V0, const __half* __restrict__ V1,
    const __half* __restrict__ V2, __half* __restrict__ ACC, long long qbase)
{
    __shared__ float sx[96], sy[96], sw[96];
    __shared__ const __half* tptr[96][4];
    __shared__ float twgt[96][4];

    long long q0 = qbase + (long long)blockIdx.x * 2;
    int t = threadIdx.x;

    if (t < 96) {
        int qi = t / 48;
        int pp = t - qi * 48;
        long long q = q0 + qi;
        int nq = (int)(q % NQ);
        int hq = nq >> 6, wq = nq & 63;
        float refx = (wq + 0.5f) * (1.f / 64.f);
        float refy = (hq + 0.5f) * (1.f / 64.f);
        const float* row = OFW + q * 144;
        sx[t] = tanhf(2.f * (refx + row[pp * 2]) - 1.f);
        sy[t] = tanhf(2.f * (refy + row[pp * 2 + 1]) - 1.f);
        sw[t] = row[96 + pp] * (sim[q] + 0.001f);
    }
    __syncthreads();
    if (t < 8) {
        float* w = sw + t * 12;
        float mx = -1e30f;
        #pragma unroll
        for (int p = 0; p < 12; p++) mx = fmaxf(mx, w[p]);
        float sum = 0.f;
        #pragma unroll
        for (int p = 0; p < 12; p++) { w[p] = expf(w[p] - mx); sum += w[p]; }
        float inv = 1.f / sum;
        #pragma unroll
        for (int p = 0; p < 12; p++) w[p] *= inv;
    }
    __syncthreads();
    if (t < 96) {
        int qi = t / 48;
        int pp = t - qi * 48;
        long long q = q0 + qi;
        int bb = (int)(q / NQ);
        int l = (pp % 12) >> 2;
        int sz = 64 >> l;
        const __half* Vb = (l == 0) ? V0 + (size_t)bb * 4096 * CC
                         : (l == 1) ? V1 + (size_t)bb * 1024 * CC
                                    : V2 + (size_t)bb * 256 * CC;
        float x = (sx[t] + 1.f) * 0.5f * (sz - 1);
        float y = (sy[t] + 1.f) * 0.5f * (sz - 1);
        float x0f = floorf(x), y0f = floorf(y);
        int x0 = (int)x0f, y0 = (int)y0f;
        float wx1 = x - x0f, wy1 = y - y0f;
        float w = sw[t];
        float wgs[4] = {(1.f - wy1) * (1.f - wx1), (1.f - wy1) * wx1,
                        wy1 * (1.f - wx1),         wy1 * wx1};
        #pragma unroll
        for (int tap = 0; tap < 4; tap++) {
            int yi = y0 + (tap >> 1), xi = x0 + (tap & 1);
            bool valid = ((unsigned)yi < (unsigned)sz) && ((unsigned)xi < (unsigned)sz);
            int yc = min(max(yi, 0), sz - 1);
            int xc = min(max(xi, 0), sz - 1);
            tptr[t][tap] = Vb + (size_t)(yc * sz + xc) * CC;
            twgt[t][tap] = valid ? w * wgs[tap] : 0.f;
        }
    }
    __syncthreads();

    int warp = t >> 5, lane = t & 31;
    int qi = warp >> 2, h = warp & 3;
    int c8 = lane * 8;

    unsigned long long acc01 = 0, acc23 = 0, acc45 = 0, acc67 = 0;

    #pragma unroll
    for (int i = 0; i < 12; i++) {
        int p = qi * 48 + h * 12 + i;
        #pragma unroll
        for (int tap = 0; tap < 4; tap++) {
            float tw = twgt[p][tap];
            unsigned long long tw2 = pack2(tw, tw);
            const uint4 raw = __ldg((const uint4*)(tptr[p][tap] + c8));
            fma_f32x2(acc01, h2_to_f2u(raw.x), tw2);
            fma_f32x2(acc23, h2_to_f2u(raw.y), tw2);
            fma_f32x2(acc45, h2_to_f2u(raw.z), tw2);
            fma_f32x2(acc67, h2_to_f2u(raw.w), tw2);
        }
    }
    float2 a01 = unpack2(acc01), a23 = unpack2(acc23);
    float2 a45 = unpack2(acc45), a67 = unpack2(acc67);
    __half* out = ACC + (q0 + qi) * 1024 + h * CC + c8;
    uint4 packed;
    packed.x = h2u(__floats2half2_rn(a01.x, a01.y));
    packed.y = h2u(__floats2half2_rn(a23.x, a23.y));
    packed.z = h2u(__floats2half2_rn(a45.x, a45.y));
    packed.w = h2u(__floats2half2_rn(a67.x, a67.y));
    *(uint4*)out = packed;
}

// ---------------- host orchestration ----------------
struct Streams {
    cudaStream_t s1, s2, s3;
    cudaEvent_t evRoot, ev1, ev2, ev3, evW, evQ, evH1;
    Streams() {
        cudaStreamCreateWithFlags(&s1, cudaStreamNonBlocking);
        cudaStreamCreateWithFlags(&s2, cudaStreamNonBlocking);
        cudaStreamCreateWithFlags(&s3, cudaStreamNonBlocking);
        cudaEventCreateWithFlags(&evRoot, cudaEventDisableTiming);
        cudaEventCreateWithFlags(&ev1, cudaEventDisableTiming);
        cudaEventCreateWithFlags(&ev2, cudaEventDisableTiming);
        cudaEventCreateWithFlags(&ev3, cudaEventDisableTiming);
        cudaEventCreateWithFlags(&evW, cudaEventDisableTiming);
        cudaEventCreateWithFlags(&evQ, cudaEventDisableTiming);
        cudaEventCreateWithFlags(&evH1, cudaEventDisableTiming);
    }
};

static void gemm_v(cudaStream_t st,
                   const float* A, long long sab, long long sam, long long sak,
                   const float* W, const float* bias,
                   __half* C, long long scb, long long scm,
                   int M, int N, int K, int batch)
{
    dim3 grid(N / BN, M / BM, batch);
    gemm_hc<<<grid, 256, 0, st>>>(A, sab, sam, sak, W, bias,
                                  (float*)C, scb, scm, 1, M, N, K, 1);
}

static void gemm_tail(cudaStream_t st,
                      const __half* A,
                      const __half* W, const float* bias,
                      const float* R, long long srm, long long srn,
                      float* C, long long scm, long long scn,
                      int M, int N, int K, int act, int half_out)
{
    cudaFuncSetAttribute(gemm_hh, cudaFuncAttributeMaxDynamicSharedMemorySize, HH_SMEM);
    dim3 grid(N / BNH, M / BM, 1);
    gemm_hh<<<grid, 256, HH_SMEM, st>>>(A, 0, W, bias, R, 0, srm, srn,
                                        C, 0, scm, scn, M, N, K, act, half_out);
}

static void gemm_prec(cudaStream_t st,
                      const float* A, long long sab, long long sam, long long sak,
                      const float* W, const float* bias,
                      float* C, long long scb, long long scm,
                      int M, int N, int K, int batch)
{
    dim3 grid((N + BN - 1) / BN, M / BM, batch);
    gemm_hc3<<<grid, 256, 0, st>>>(A, sab, sam, sak, W, bias, C, scb, scm, M, N, K);
}

extern "C" void kernel_launch(void* const* d_in, const int* in_sizes, int n_in,
                              void* d_out, int out_size)
{
    static Streams str;

    const float* S     = (const float*)d_in[0];
    const float* f0    = (const float*)d_in[1];
    const float* f1    = (const float*)d_in[2];
    const float* f2    = (const float*)d_in[3];
    const float* sim   = (const float*)d_in[4];
    const float* vw0   = (const float*)d_in[5];
    const float* vb0   = (const float*)d_in[6];
    const float* vw1   = (const float*)d_in[7];
    const float* vb1   = (const float*)d_in[8];
    const float* vw2   = (const float*)d_in[9];
    const float* vb2   = (const float*)d_in[10];
    const float* q_w   = (const float*)d_in[11];
    const float* q_b   = (const float*)d_in[12];
    const float* off_w = (const float*)d_in[13];
    const float* off_b = (const float*)d_in[14];
    const float* wgt_w = (const float*)d_in[15];
    const float* wgt_b = (const float*)d_in[16];
    const float* out_w = (const float*)d_in[17];
    const float* out_b = (const float*)d_in[18];
    const float* lnq_g = (const float*)d_in[19];
    const float* lnq_b = (const float*)d_in[20];
    const float* lno_g = (const float*)d_in[21];
    const float* lno_b = (const float*)d_in[22];
    const float* fc1_w = (const float*)d_in[23];
    const float* fc1_b = (const float*)d_in[24];
    const float* fc2_w = (const float*)d_in[25];
    const float* fc2_b = (const float*)d_in[26];
    float* outp = (float*)d_out;

    float *Q, *OFW, *OW, *OWb, *Y, *Z;
    __half *V0h, *V1h, *V2h, *ACCh, *Zh, *Hh, *OutWh, *F1Wh, *F2Wh;
    cudaGetSymbolAddress((void**)&Q,     g_Q);
    cudaGetSymbolAddress((void**)&V0h,   g_V0h);
    cudaGetSymbolAddress((void**)&V1h,   g_V1h);
    cudaGetSymbolAddress((void**)&V2h,   g_V2h);
    cudaGetSymbolAddress((void**)&OFW,   g_OFW);
    cudaGetSymbolAddress((void**)&OW,    g_OW);
    cudaGetSymbolAddress((void**)&OWb,   g_OWb);
    cudaGetSymbolAddress((void**)&ACCh,  g_ACCh);
    cudaGetSymbolAddress((void**)&Y,     g_Y);
    cudaGetSymbolAddress((void**)&Z,     g_Z);
    cudaGetSymbolAddress((void**)&Zh,    g_Zh);
    cudaGetSymbolAddress((void**)&Hh,    g_Hh);
    cudaGetSymbolAddress((void**)&OutWh, g_OutWh);
    cudaGetSymbolAddress((void**)&F1Wh,  g_F1Wh);
    cudaGetSymbolAddress((void**)&F2Wh,  g_F2Wh);

    cudaStream_t s0 = 0;

    // fork everything off s0 immediately
    cudaEventRecord(str.evRoot, s0);
    cudaStreamWaitEvent(str.s1, str.evRoot, 0);
    cudaStreamWaitEvent(str.s2, str.evRoot, 0);
    cudaStreamWaitEvent(str.s3, str.evRoot, 0);

    // s1: V0 projection starts immediately (largest, sampler dependency)
    gemm_v(str.s1, f0, (long long)256 * 4096, 1, 4096, vw0, vb0,
           V0h, (long long)4096 * CC, CC, 4096, CC, 256, BB);
    cudaEventRecord(str.ev1, str.s1);

    // s2: setup kernels (off critical path) + V1 projection
    pack_kernel<<<(144 * CC + 144 + 255) / 256, 256, 0, str.s2>>>(off_w, wgt_w, off_b, wgt_b, OW, OWb);
    w2h_kernel<<<1024, 256, 0, str.s2>>>(out_w, fc1_w, fc2_w, OutWh, F1Wh, F2Wh);
    cudaEventRecord(str.evW, str.s2);
    gemm_v(str.s2, f1, (long long)512 * 1024, 1, 1024, vw1, vb1,
           V1h, (long long)1024 * CC, CC, 1024, CC, 512, BB);
    cudaEventRecord(str.ev2, str.s2);

    // s3: V2 projection (tiny; s3 later runs the half1 chain)
    gemm_v(str.s3, f2, (long long)1024 * 256, 1, 256, vw2, vb2,
           V2h, (long long)256 * CC, CC, 256, CC, 1024, BB);
    cudaEventRecord(str.ev3, str.s3);

    // ---- shared prefix on s0: q projection + LN over both batches ----
    gemm_prec(s0, S, (long long)CC * NQ, 1, NQ, q_w, q_b,
              Q, (long long)NQ * CC, CC, NQ, CC, CC, BB);
    ln_kernel<<<BB * NQ / 8, 256, 0, s0>>>(Q, lnq_g, lnq_b);
    cudaEventRecord(str.evQ, s0);

    // ---- pipelined per-batch chains: half0 on s0, half1 on s3 ----
    cudaStreamWaitEvent(str.s3, str.evQ, 0);

    // half1 chain on s3 (V2 already ordered on s3)
    {
        const long long r1 = (long long)NQ;
        cudaStreamWaitEvent(str.s3, str.evW, 0);
        gemm_prec(str.s3, Q + r1 * CC, 0, CC, 1, OW, OWb,
                  OFW + r1 * 144, 0, 144, NQ, 144, CC, 1);
        cudaStreamWaitEvent(str.s3, str.ev1, 0);
        cudaStreamWaitEvent(str.s3, str.ev2, 0);
        sample_kernel<<<NQ / 2, 256, 0, str.s3>>>(OFW, sim, V0h, V1h, V2h, ACCh, r1);
        gemm_tail(str.s3, ACCh + r1 * 1024, OutWh, out_b, nullptr, 0, 0,
                  Y + r1 * CC, CC, 1, NQ, CC, 1024, 0, 0);
        add_ln_kernel<<<NQ / 32, 256, 0, str.s3>>>(S, Y, Z, Zh, lno_g, lno_b, 1);
        gemm_tail(str.s3, Zh + r1 * CC, F1Wh, fc1_b, nullptr, 0, 0,
                  (float*)(Hh + r1 * 1024), 1024, 1, NQ, 1024, CC, 1, 1);
        gemm_tail(str.s3, Hh + r1 * 1024, F2Wh, fc2_b,
                  Z + r1 * CC, CC, 1,
                  outp + (long long)CC * NQ, 1, NQ, NQ, CC, 1024, 0, 0);
        cudaEventRecord(str.evH1, str.s3);
    }

    // half0 chain on s0
    {
        cudaStreamWaitEvent(s0, str.evW, 0);
        gemm_prec(s0, Q, 0, CC, 1, OW, OWb, OFW, 0, 144, NQ, 144, CC, 1);
        cudaStreamWaitEvent(s0, str.ev1, 0);
        cudaStreamWaitEvent(s0, str.ev2, 0);
        cudaStreamWaitEvent(s0, str.ev3, 0);
        sample_kernel<<<NQ / 2, 256, 0, s0>>>(OFW, sim, V0h, V1h, V2h, ACCh, 0);
        gemm_tail(s0, ACCh, OutWh, out_b, nullptr, 0, 0,
                  Y, CC, 1, NQ, CC, 1024, 0, 0);
        add_ln_kernel<<<NQ / 32, 256, 0, s0>>>(S, Y, Z, Zh, lno_g, lno_b, 0);
        gemm_tail(s0, Zh, F1Wh, fc1_b, nullptr, 0, 0,
                  (float*)Hh, 1024, 1, NQ, 1024, CC, 1, 1);
        gemm_tail(s0, Hh, F2Wh, fc2_b,
                  Z, CC, 1,
                  outp, 1, NQ, NQ, CC, 1024, 0, 0);
    }

    // join
    cudaStreamWaitEvent(s0, str.evH1, 0);
}

// round 16
// speedup vs baseline: 1.0850x; 1.0850x over previous
#include <cuda_runtime.h>
#include <cuda_fp16.h>
#include <math.h>

#define BB 2
#define CC 256
#define NQ 4096

// ---------------- scratch ----------------
__device__ float  g_Q  [BB*NQ*CC];
__device__ __half g_V0h[BB*4096*CC];
__device__ __half g_V1h[BB*1024*CC];
__device__ __half g_V2h[BB*256*CC];
__device__ float  g_OFW[BB*NQ*144];
__device__ float  g_OW [144*CC];
__device__ float  g_OWb[144];
__device__ __half g_ACCh[(size_t)BB*NQ*1024];
__device__ float  g_Y  [BB*NQ*CC];
__device__ float  g_Z  [BB*NQ*CC];
__device__ __half g_Zh [BB*NQ*CC];
__device__ __half g_Hh [(size_t)BB*NQ*1024];
__device__ __half g_OutWh[256*1024];
__device__ __half g_F1Wh [1024*256];
__device__ __half g_F2Wh [256*1024];

#define BM 128
#define BN 64

// ---------------- helpers ----------------
__device__ __forceinline__ void mma16(float d[4],
                                      unsigned a0, unsigned a1, unsigned a2, unsigned a3,
                                      unsigned b0, unsigned b1)
{
    asm volatile(
        "mma.sync.aligned.m16n8k16.row.col.f32.f16.f16.f32 "
        "{%0,%1,%2,%3},{%4,%5,%6,%7},{%8,%9},{%0,%1,%2,%3};"
        : "+f"(d[0]), "+f"(d[1]), "+f"(d[2]), "+f"(d[3])
        : "r"(a0), "r"(a1), "r"(a2), "r"(a3), "r"(b0), "r"(b1));
}

__device__ __forceinline__ void ldsm_x4(unsigned& r0, unsigned& r1, unsigned& r2, unsigned& r3,
                                        unsigned addr)
{
    asm volatile("ldmatrix.sync.aligned.m8n8.x4.shared.b16 {%0,%1,%2,%3},[%4];"
                 : "=r"(r0), "=r"(r1), "=r"(r2), "=r"(r3) : "r"(addr));
}

__device__ __forceinline__ void ldsm_x4_t(unsigned& r0, unsigned& r1, unsigned& r2, unsigned& r3,
                                          unsigned addr)
{
    asm volatile("ldmatrix.sync.aligned.m8n8.x4.trans.shared.b16 {%0,%1,%2,%3},[%4];"
                 : "=r"(r0), "=r"(r1), "=r"(r2), "=r"(r3) : "r"(addr));
}

__device__ __forceinline__ unsigned h2u(__half2 h) { return *(unsigned*)&h; }

__device__ __forceinline__ float gelu_exact(float v)
{
    return 0.5f * v * (1.f + erff(v * 0.70710678118654752f));
}

__device__ __forceinline__ void fma_f32x2(unsigned long long& acc,
                                          unsigned long long v, unsigned long long w)
{
    asm("fma.rn.f32x2 %0, %1, %2, %0;" : "+l"(acc) : "l"(v), "l"(w));
}
__device__ __forceinline__ unsigned long long pack2(float lo, float hi)
{
    unsigned long long r;
    asm("mov.b64 %0, {%1, %2};" : "=l"(r) : "f"(lo), "f"(hi));
    return r;
}
__device__ __forceinline__ float2 unpack2(unsigned long long v)
{
    float2 r;
    asm("mov.b64 {%0, %1}, %2;" : "=f"(r.x), "=f"(r.y) : "l"(v));
    return r;
}
__device__ __forceinline__ unsigned long long h2_to_f2u(unsigned h2raw)
{
    __half2 h = *(__half2*)&h2raw;
    float2 f = __half22float2(h);
    return pack2(f.x, f.y);
}

#define CPA16(dst, src) asm volatile("cp.async.cg.shared.global [%0], [%1], 16;" :: "r"(dst), "l"(src))

// =====================================================================
// gemm_hh: pure-fp16 GEMM, 3-stage cp.async pipeline (dynamic smem).
// scn!=1 path: smem-transposed, coalesced float4 stores along m.
// =====================================================================
#define BNH 128
#define HH_STAGE_BYTES 10240
#define HH_SMEM (3 * 2 * HH_STAGE_BYTES)

__global__ void __launch_bounds__(256, 2) gemm_hh(
    const __half* __restrict__ A, long long sab,
    const __half* __restrict__ W,
    const float* __restrict__ bias,
    const float* __restrict__ R, long long srb, long long srm, long long srn,
    float* __restrict__ Cout, long long scb, long long scm, long long scn,
    int M, int N, int K, int act, int half_out)
{
    extern __shared__ __align__(16) __half sm_hh[];
    __half* Ahs = sm_hh;
    __half* Bhs = sm_hh + 3 * 5120;

    const int tid = threadIdx.x;
    const int lane = tid & 31, warp = tid >> 5;
    const int g = lane >> 2, tg = lane & 3;
    const int wm = (warp >> 2) * 64, wn = (warp & 3) * 32;
    const int m0 = blockIdx.y * BM, n0 = blockIdx.x * BNH;

    A += (long long)blockIdx.z * sab;
    if (R) R += (long long)blockIdx.z * srb;
    float* CoutF = Cout + (long long)blockIdx.z * scb;
    __half* CoutH = (__half*)Cout + (long long)blockIdx.z * scb;

    const unsigned aS = (unsigned)__cvta_generic_to_shared(Ahs);
    const unsigned bS = (unsigned)__cvta_generic_to_shared(Bhs);

    const int r0 = tid >> 2, c0 = tid & 3;
    const int r1 = r0 + 64;
    const unsigned dA0 = (unsigned)((r0 * 40 + c0 * 8) * 2);
    const unsigned dA1 = (unsigned)((r1 * 40 + c0 * 8) * 2);

#define LOADHH(stg, k0_)                                                                   \
    {                                                                                      \
        CPA16(aS + (stg) * HH_STAGE_BYTES + dA0, A + (long long)(m0 + r0) * K + (k0_) + c0 * 8); \
        CPA16(aS + (stg) * HH_STAGE_BYTES + dA1, A + (long long)(m0 + r1) * K + (k0_) + c0 * 8); \
        CPA16(bS + (stg) * HH_STAGE_BYTES + dA0, W + (long long)(n0 + r0) * K + (k0_) + c0 * 8); \
        CPA16(bS + (stg) * HH_STAGE_BYTES + dA1, W + (long long)(n0 + r1) * K + (k0_) + c0 * 8); \
        asm volatile("cp.async.commit_group;");                                            \
    }

    const unsigned offA  = (unsigned)(((wm + (lane & 7) + 8 * ((lane >> 3) & 1)) * 40 + 8 * (lane >> 4)) * 2);
    const unsigned offB0 = (unsigned)(((wn + (lane & 7) + 8 * (lane >> 4)) * 40 + 8 * ((lane >> 3) & 1)) * 2);
    const unsigned offB1 = (unsigned)(((wn + 16 + (lane & 7) + 8 * (lane >> 4)) * 40 + 8 * ((lane >> 3) & 1)) * 2);

    const int nk = K / 32;
    LOADHH(0, 0);
    LOADHH(1, 32);

    float acc[4][4][4] = {};

    for (int t = 0; t < nk; t++) {
        const int s = t % 3;
        if (t + 1 < nk) asm volatile("cp.async.wait_group 1;");
        else            asm volatile("cp.async.wait_group 0;");
        __syncthreads();

        #pragma unroll
        for (int ks = 0; ks < 2; ks++) {
            unsigned q0, q1, q2, q3, q4, q5, q6, q7;
            ldsm_x4(q0, q1, q2, q3, bS + s * HH_STAGE_BYTES + offB0 + ks * 32);
            ldsm_x4(q4, q5, q6, q7, bS + s * HH_STAGE_BYTES + offB1 + ks * 32);
            #pragma unroll
            for (int mt = 0; mt < 4; mt++) {
                unsigned f0, f1, f2, f3;
                ldsm_x4(f0, f1, f2, f3, aS + s * HH_STAGE_BYTES + offA + mt * 1280 + ks * 32);
                mma16(acc[mt][0], f0, f1, f2, f3, q0, q1);
                mma16(acc[mt][1], f0, f1, f2, f3, q2, q3);
                mma16(acc[mt][2], f0, f1, f2, f3, q4, q5);
                mma16(acc[mt][3], f0, f1, f2, f3, q6, q7);
            }
        }
        if (t + 2 < nk) { LOADHH((t + 2) % 3, (t + 2) * 32); }
    }
#undef LOADHH

    if (scn != 1 && !half_out) {
        // transposed-output path (fc2): apply bias/act/residual, then
        // smem-stage and store coalesced float4 along m.
        #pragma unroll
        for (int mt = 0; mt < 4; mt++) {
            int gm0 = m0 + wm + 16 * mt + g;
            #pragma unroll
            for (int nt = 0; nt < 4; nt++) {
                int gn0 = n0 + wn + 8 * nt + 2 * tg;
                float b0 = bias ? bias[gn0] : 0.f;
                float b1 = bias ? bias[gn0 + 1] : 0.f;
                acc[mt][nt][0] += b0; acc[mt][nt][1] += b1;
                acc[mt][nt][2] += b0; acc[mt][nt][3] += b1;
                if (act) {
                    acc[mt][nt][0] = gelu_exact(acc[mt][nt][0]);
                    acc[mt][nt][1] = gelu_exact(acc[mt][nt][1]);
                    acc[mt][nt][2] = gelu_exact(acc[mt][nt][2]);
                    acc[mt][nt][3] = gelu_exact(acc[mt][nt][3]);
                }
                if (R) {
                    acc[mt][nt][0] += R[(long long)gm0 * srm + (long long)gn0 * srn];
                    acc[mt][nt][1] += R[(long long)gm0 * srm + (long long)(gn0 + 1) * srn];
                    acc[mt][nt][2] += R[(long long)(gm0 + 8) * srm + (long long)gn0 * srn];
                    acc[mt][nt][3] += R[(long long)(gm0 + 8) * srm + (long long)(gn0 + 1) * srn];
                }
            }
        }
        float* fbuf = (float*)sm_hh;   // 64 cols x 132 floats = 33792 B <= HH_SMEM
        #pragma unroll
        for (int ph = 0; ph < 2; ph++) {
            __syncthreads();
            if (((warp & 3) >> 1) == ph) {
                #pragma unroll
                for (int mt = 0; mt < 4; mt++) {
                    int gmb = wm + 16 * mt + g;
                    #pragma unroll
                    for (int nt = 0; nt < 4; nt++) {
                        int gnb = wn + 8 * nt + 2 * tg - ph * 64;
                        fbuf[gnb * 132 + gmb]           = acc[mt][nt][0];
                        fbuf[(gnb + 1) * 132 + gmb]     = acc[mt][nt][1];
                        fbuf[gnb * 132 + gmb + 8]       = acc[mt][nt][2];
                        fbuf[(gnb + 1) * 132 + gmb + 8] = acc[mt][nt][3];
                    }
                }
            }
            __syncthreads();
            int col = tid >> 2, mo = (tid & 3) * 4;
            long long gn = n0 + ph * 64 + col;
            float* outc = CoutF + gn * scn + m0;
            #pragma unroll
            for (int k = 0; k < 8; k++) {
                float4 v = *(float4*)&fbuf[col * 132 + mo + k * 16];
                *(float4*)(outc + mo + k * 16) = v;
            }
        }
        return;
    }

    #pragma unroll
    for (int mt = 0; mt < 4; mt++) {
        int gm0 = m0 + wm + 16 * mt + g;
        #pragma unroll
        for (int nt = 0; nt < 4; nt++) {
            int gn0 = n0 + wn + 8 * nt + 2 * tg;
            float v0 = acc[mt][nt][0], v1 = acc[mt][nt][1];
            float v2 = acc[mt][nt][2], v3 = acc[mt][nt][3];
            if (bias) {
                float b0 = bias[gn0], b1 = bias[gn0 + 1];
                v0 += b0; v1 += b1; v2 += b0; v3 += b1;
            }
            if (act) {
                v0 = gelu_exact(v0); v1 = gelu_exact(v1);
                v2 = gelu_exact(v2); v3 = gelu_exact(v3);
            }
            if (R) {
                v0 += R[(long long)gm0 * srm + (long long)gn0 * srn];
                v1 += R[(long long)gm0 * srm + (long long)(gn0 + 1) * srn];
                v2 += R[(long long)(gm0 + 8) * srm + (long long)gn0 * srn];
                v3 += R[(long long)(gm0 + 8) * srm + (long long)(gn0 + 1) * srn];
            }
            if (half_out) {
                *(__half2*)(CoutH + (long long)gm0 * scm + gn0)       = __floats2half2_rn(v0, v1);
                *(__half2*)(CoutH + (long long)(gm0 + 8) * scm + gn0) = __floats2half2_rn(v2, v3);
            } else {
                *(float2*)(CoutF + (long long)gm0 * scm + gn0)       = make_float2(v0, v1);
                *(float2*)(CoutF + (long long)(gm0 + 8) * scm + gn0) = make_float2(v2, v3);
            }
        }
    }
}

// =====================================================================
// gemm_hc: fp16 TC GEMM with fp32 inputs (V projections only).
// =====================================================================
__global__ void __launch_bounds__(256, 2) gemm_hc(
    const float* __restrict__ A, long long sab, long long sam, long long sak,
    const float* __restrict__ W,
    const float* __restrict__ bias,
    float* __restrict__ Cout, long long scb, long long scm, long long scn,
    int M, int N, int K, int half_out)
{
    __shared__ __align__(16) __half As[2][5120];
    __shared__ __align__(16) __half Bs[2][2560];

    const int tid = threadIdx.x;
    const int lane = tid & 31, warp = tid >> 5;
    const int g = lane >> 2, tg = lane & 3;
    const int wm = (warp >> 2) * 64, wn = (warp & 3) * 16;
    const int m0 = blockIdx.y * BM, n0 = blockIdx.x * BN;
    const bool kc = (sak == 1);

    A += (long long)blockIdx.z * sab;
    float* CoutF = Cout + (long long)blockIdx.z * scb;
    __half* CoutH = (__half*)Cout + (long long)blockIdx.z * scb;

    const unsigned aBase = (unsigned)__cvta_generic_to_shared(&As[0][0]);
    const unsigned bBase = (unsigned)__cvta_generic_to_shared(&Bs[0][0]);

    unsigned offA;
    if (kc) offA = (unsigned)(((wm + (lane & 7) + 8 * ((lane >> 3) & 1)) * 40 + 8 * (lane >> 4)) * 2);
    else    offA = (unsigned)((((lane & 7) + 8 * ((lane >> 4) & 1)) * 136 + wm + 8 * ((lane >> 3) & 1)) * 2);
    const unsigned offB = (unsigned)(((wn + (lane & 7) + 8 * (lane >> 4)) * 40 + 8 * ((lane >> 3) & 1)) * 2);

    float4 a0_, a1_, a2_, a3_, b0_, b1_;

#define GLOAD(k0_)                                                                          \
    if (kc) {                                                                               \
        const float* p = A + (long long)(m0 + (tid >> 1)) * sam + (k0_) + (tid & 1) * 16;   \
        a0_ = *(const float4*)p;        a1_ = *(const float4*)(p + 4);                      \
        a2_ = *(const float4*)(p + 8);  a3_ = *(const float4*)(p + 12);                     \
    } else {                                                                                \
        const float* p = A + (long long)((k0_) + (tid >> 3)) * sak + m0 + (tid & 7) * 16;   \
        a0_ = *(const float4*)p;        a1_ = *(const float4*)(p + 4);                      \
        a2_ = *(const float4*)(p + 8);  a3_ = *(const float4*)(p + 12);                     \
    }                                                                                       \
    {                                                                                       \
        const float* p = W + (long long)(n0 + (tid >> 2)) * K + (k0_) + (tid & 3) * 8;      \
        b0_ = *(const float4*)p;        b1_ = *(const float4*)(p + 4);                      \
    }

#define SSTORE(buf)                                                                         \
    {                                                                                       \
        uint4 v0, v1;                                                                       \
        v0.x = h2u(__floats2half2_rn(a0_.x, a0_.y)); v0.y = h2u(__floats2half2_rn(a0_.z, a0_.w)); \
        v0.z = h2u(__floats2half2_rn(a1_.x, a1_.y)); v0.w = h2u(__floats2half2_rn(a1_.z, a1_.w)); \
        v1.x = h2u(__floats2half2_rn(a2_.x, a2_.y)); v1.y = h2u(__floats2half2_rn(a2_.z, a2_.w)); \
        v1.z = h2u(__floats2half2_rn(a3_.x, a3_.y)); v1.w = h2u(__floats2half2_rn(a3_.z, a3_.w)); \
        __half* d;                                                                          \
        if (kc) d = &As[buf][(tid >> 1) * 40 + (tid & 1) * 16];                             \
        else    d = &As[buf][(tid >> 3) * 136 + (tid & 7) * 16];                            \
        *(uint4*)d = v0; *(uint4*)(d + 8) = v1;                                             \
        uint4 vb;                                                                           \
        vb.x = h2u(__floats2half2_rn(b0_.x, b0_.y)); vb.y = h2u(__floats2half2_rn(b0_.z, b0_.w)); \
        vb.z = h2u(__floats2half2_rn(b1_.x, b1_.y)); vb.w = h2u(__floats2half2_rn(b1_.z, b1_.w)); \
        *(uint4*)&Bs[buf][(tid >> 2) * 40 + (tid & 3) * 8] = vb;                            \
    }

    GLOAD(0); SSTORE(0);
    __syncthreads();

    float acc[4][2][4] = {};
    const int nk = K / 32;

    for (int t = 0; t < nk; t++) {
        const int buf = t & 1;
        const bool more = (t + 1 < nk);
        if (more) { GLOAD((t + 1) * 32); }

        #pragma unroll
        for (int ks = 0; ks < 2; ks++) {
            unsigned q0, q1, q2, q3;
            ldsm_x4(q0, q1, q2, q3, bBase + buf * 5120 + offB + ks * 32);
            #pragma unroll
            for (int mt = 0; mt < 4; mt++) {
                unsigned f0, f1, f2, f3;
                if (kc) ldsm_x4  (f0, f1, f2, f3, aBase + buf * 10240 + offA + mt * 1280 + ks * 32);
                else    ldsm_x4_t(f0, f1, f2, f3, aBase + buf * 10240 + offA + mt * 32 + ks * 4352);
                mma16(acc[mt][0], f0, f1, f2, f3, q0, q1);
                mma16(acc[mt][1], f0, f1, f2, f3, q2, q3);
            }
        }
        if (more) { SSTORE(buf ^ 1); }
        __syncthreads();
    }
#undef GLOAD
#undef SSTORE

    #pragma unroll
    for (int mt = 0; mt < 4; mt++) {
        int gm0 = m0 + wm + 16 * mt + g;
        #pragma unroll
        for (int nt = 0; nt < 2; nt++) {
            int gn0 = n0 + wn + 8 * nt + 2 * tg;
            float v0 = acc[mt][nt][0], v1 = acc[mt][nt][1];
            float v2 = acc[mt][nt][2], v3 = acc[mt][nt][3];
            if (bias) {
                float b0 = bias[gn0], b1 = bias[gn0 + 1];
                v0 += b0; v1 += b1; v2 += b0; v3 += b1;
            }
            if (half_out) {
                *(__half2*)(CoutH + (long long)gm0 * scm + gn0)       = __floats2half2_rn(v0, v1);
                *(__half2*)(CoutH + (long long)(gm0 + 8) * scm + gn0) = __floats2half2_rn(v2, v3);
            } else {
                *(float2*)(CoutF + (long long)gm0 * scm + gn0)       = make_float2(v0, v1);
                *(float2*)(CoutF + (long long)(gm0 + 8) * scm + gn0) = make_float2(v2, v3);
            }
        }
    }
}

// =====================================================================
// gemm_hc3: 3xFP16 hi/lo-split precise GEMM.
// =====================================================================
__global__ void __launch_bounds__(256, 2) gemm_hc3(
    const float* __restrict__ A, long long sab, long long sam, long long sak,
    const float* __restrict__ W,
    const float* __restrict__ bias,
    float* __restrict__ Cout, long long scb, long long scm,
    int M, int N, int K)
{
    __shared__ __align__(16) __half Ahs[2][3072];
    __shared__ __align__(16) __half Als[2][3072];
    __shared__ __align__(16) __half Bhs[2][1536];
    __shared__ __align__(16) __half Bls[2][1536];

    const int tid = threadIdx.x;
    const int lane = tid & 31, warp = tid >> 5;
    const int g = lane >> 2, tg = lane & 3;
    const int wm = (warp >> 2) * 64, wn = (warp & 3) * 16;
    const int m0 = blockIdx.y * BM, n0 = blockIdx.x * BN;
    const bool kc = (sak == 1);

    A    += (long long)blockIdx.z * sab;
    Cout += (long long)blockIdx.z * scb;

    const unsigned ahB = (unsigned)__cvta_generic_to_shared(&Ahs[0][0]);
    const unsigned alB = (unsigned)__cvta_generic_to_shared(&Als[0][0]);
    const unsigned bhB = (unsigned)__cvta_generic_to_shared(&Bhs[0][0]);
    const unsigned blB = (unsigned)__cvta_generic_to_shared(&Bls[0][0]);

    unsigned offA;
    if (kc) offA = (unsigned)(((wm + (lane & 15)) * 24 + 8 * (lane >> 4)) * 2);
    else    offA = (unsigned)((((lane & 7) + 8 * ((lane >> 4) & 1)) * 136 + wm + 8 * ((lane >> 3) & 1)) * 2);
    const unsigned offB = (unsigned)(((wn + (lane & 7) + 8 * (lane >> 4)) * 24 + 8 * ((lane >> 3) & 1)) * 2);

    float4 rA0, rA1, rB;

#define GLOAD3(k0_)                                                                         \
    if (kc) {                                                                               \
        const float* p = A + (long long)(m0 + (tid >> 1)) * sam + (k0_) + (tid & 1) * 8;    \
        rA0 = *(const float4*)p;  rA1 = *(const float4*)(p + 4);                            \
    } else {                                                                                \
        const float* p = A + (long long)((k0_) + (tid >> 4)) * sak + m0 + (tid & 15) * 8;   \
        rA0 = *(const float4*)p;  rA1 = *(const float4*)(p + 4);                            \
    }                                                                                       \
    {   int gn_ = n0 + (tid >> 2);                                                          \
        rB = (gn_ < N) ? *(const float4*)(W + (long long)gn_ * K + (k0_) + (tid & 3) * 4)   \
                       : make_float4(0.f, 0.f, 0.f, 0.f); }

#define SPL(x, h_, l_) { h_ = __float2half_rn(x); l_ = __float2half_rn((x) - __half2float(h_)); }

#define SSTORE3(buf)                                                                        \
    {                                                                                       \
        __half h0,h1,h2,h3,h4,h5,h6,h7, l0,l1,l2,l3,l4,l5,l6,l7;                            \
        SPL(rA0.x,h0,l0); SPL(rA0.y,h1,l1); SPL(rA0.z,h2,l2); SPL(rA0.w,h3,l3);             \
        SPL(rA1.x,h4,l4); SPL(rA1.y,h5,l5); SPL(rA1.z,h6,l6); SPL(rA1.w,h7,l7);             \
        unsigned dof;                                                                       \
        if (kc) dof = (tid >> 1) * 24 + (tid & 1) * 8;                                      \
        else    dof = (tid >> 4) * 136 + (tid & 15) * 8;                                    \
        uint4 vh, vl;                                                                       \
        vh.x = h2u(__halves2half2(h0,h1)); vh.y = h2u(__halves2half2(h2,h3));               \
        vh.z = h2u(__halves2half2(h4,h5)); vh.w = h2u(__halves2half2(h6,h7));               \
        vl.x = h2u(__halves2half2(l0,l1)); vl.y = h2u(__halves2half2(l2,l3));               \
        vl.z = h2u(__halves2half2(l4,l5)); vl.w = h2u(__halves2half2(l6,l7));               \
        *(uint4*)&Ahs[buf][dof] = vh;  *(uint4*)&Als[buf][dof] = vl;                        \
        __half bh0,bh1,bh2,bh3, bl0,bl1,bl2,bl3;                                            \
        SPL(rB.x,bh0,bl0); SPL(rB.y,bh1,bl1); SPL(rB.z,bh2,bl2); SPL(rB.w,bh3,bl3);         \
        unsigned bof = (tid >> 2) * 24 + (tid & 3) * 4;                                     \
        uint2 wh, wl;                                                                       \
        wh.x = h2u(__halves2half2(bh0,bh1)); wh.y = h2u(__halves2half2(bh2,bh3));           \
        wl.x = h2u(__halves2half2(bl0,bl1)); wl.y = h2u(__halves2half2(bl2,bl3));           \
        *(uint2*)&Bhs[buf][bof] = wh;  *(uint2*)&Bls[buf][bof] = wl;                        \
    }

    GLOAD3(0); SSTORE3(0);
    __syncthreads();

    float acc[4][2][4] = {};
    const int nk = K / 16;

    for (int t = 0; t < nk; t++) {
        const int buf = t & 1;
        const bool more = (t + 1 < nk);
        if (more) { GLOAD3((t + 1) * 16); }

        unsigned qh0, qh1, qh2, qh3, ql0, ql1, ql2, ql3;
        ldsm_x4(qh0, qh1, qh2, qh3, bhB + buf * 3072 + offB);
        ldsm_x4(ql0, ql1, ql2, ql3, blB + buf * 3072 + offB);

        #pragma unroll
        for (int mt = 0; mt < 4; mt++) {
            unsigned fh0, fh1, fh2, fh3, fl0, fl1, fl2, fl3;
            if (kc) {
                ldsm_x4  (fh0, fh1, fh2, fh3, ahB + buf * 6144 + offA + mt * 768);
                ldsm_x4  (fl0, fl1, fl2, fl3, alB + buf * 6144 + offA + mt * 768);
            } else {
                ldsm_x4_t(fh0, fh1, fh2, fh3, ahB + buf * 6144 + offA + mt * 32);
                ldsm_x4_t(fl0, fl1, fl2, fl3, alB + buf * 6144 + offA + mt * 32);
            }
            mma16(acc[mt][0], fl0, fl1, fl2, fl3, qh0, qh1);
            mma16(acc[mt][0], fh0, fh1, fh2, fh3, ql0, ql1);
            mma16(acc[mt][0], fh0, fh1, fh2, fh3, qh0, qh1);
            mma16(acc[mt][1], fl0, fl1, fl2, fl3, qh2, qh3);
            mma16(acc[mt][1], fh0, fh1, fh2, fh3, ql2, ql3);
            mma16(acc[mt][1], fh0, fh1, fh2, fh3, qh2, qh3);
        }
        if (more) { SSTORE3(buf ^ 1); }
        __syncthreads();
    }
#undef GLOAD3
#undef SSTORE3
#undef SPL

    #pragma unroll
    for (int mt = 0; mt < 4; mt++) {
        int gm0 = m0 + wm + 16 * mt + g;
        #pragma unroll
        for (int nt = 0; nt < 2; nt++) {
            int gn0 = n0 + wn + 8 * nt + 2 * tg;
            if (gn0 >= N) continue;
            float v0 = acc[mt][nt][0], v1 = acc[mt][nt][1];
            float v2 = acc[mt][nt][2], v3 = acc[mt][nt][3];
            if (bias) {
                float b0 = bias[gn0], b1 = bias[gn0 + 1];
                v0 += b0; v1 += b1; v2 += b0; v3 += b1;
            }
            *(float2*)(Cout + (long long)gm0 * scm + gn0)       = make_float2(v0, v1);
            *(float2*)(Cout + (long long)(gm0 + 8) * scm + gn0) = make_float2(v2, v3);
        }
    }
}

// ---------------- warp-per-row LN ----------------
__global__ void ln_kernel(float* __restrict__ X,
                          const float* __restrict__ g, const float* __restrict__ b)
{
    long long row = (long long)blockIdx.x * 8 + (threadIdx.x >> 5);
    int lane = threadIdx.x & 31;
    float* xr = X + row * CC;

    float v[8];
    float s = 0.f;
    #pragma unroll
    for (int j = 0; j < 8; j++) { v[j] = xr[lane + 32 * j]; s += v[j]; }
    #pragma unroll
    for (int o = 16; o; o >>= 1) s += __shfl_xor_sync(0xffffffffu, s, o);
    float mu = s * (1.f / CC);
    float s2 = 0.f;
    #pragma unroll
    for (int j = 0; j < 8; j++) { v[j] -= mu; s2 += v[j] * v[j]; }
    #pragma unroll
    for (int o = 16; o; o >>= 1) s2 += __shfl_xor_sync(0xffffffffu, s2, o);
    float r = rsqrtf(s2 * (1.f / CC) + 1e-5f);
    #pragma unroll
    for (int j = 0; j < 8; j++)
        xr[lane + 32 * j] = v[j] * r * g[lane + 32 * j] + b[lane + 32 * j];
}

// ---------------- add+LN (per-batch), writes Z fp32 + Zh fp16 ----------------
__global__ void __launch_bounds__(256) add_ln_kernel(
    const float* __restrict__ S, const float* __restrict__ Y,
    float* __restrict__ Z, __half* __restrict__ Zh,
    const float* __restrict__ g, const float* __restrict__ b_, int bb)
{
    __shared__ float Sv[CC][33];

    long long nq0 = (long long)blockIdx.x * 32;
    int tid = threadIdx.x;

    const float* Sb = S + (long long)bb * CC * NQ + nq0;
    for (int i = tid; i < CC * 32; i += 256) {
        int c = i >> 5, qi = i & 31;
        Sv[c][qi] = Sb[(long long)c * NQ + qi];
    }
    __syncthreads();

    int lane = tid & 31, warp = tid >> 5;
    #pragma unroll
    for (int it = 0; it < 4; it++) {
        int qi = warp + it * 8;
        long long row = ((long long)bb * NQ + nq0 + qi);
        const float* yr = Y + row * CC;
        float v[8];
        float s = 0.f;
        #pragma unroll
        for (int j = 0; j < 8; j++) {
            int c = lane + 32 * j;
            v[j] = Sv[c][qi] + yr[c];
            s += v[j];
        }
        #pragma unroll
        for (int o = 16; o; o >>= 1) s += __shfl_xor_sync(0xffffffffu, s, o);
        float mu = s * (1.f / CC);
        float s2 = 0.f;
        #pragma unroll
        for (int j = 0; j < 8; j++) { v[j] -= mu; s2 += v[j] * v[j]; }
        #pragma unroll
        for (int o = 16; o; o >>= 1) s2 += __shfl_xor_sync(0xffffffffu, s2, o);
        float r = rsqrtf(s2 * (1.f / CC) + 1e-5f);
        float* zr = Z + row * CC;
        __half* zh = Zh + row * CC;
        #pragma unroll
        for (int j = 0; j < 8; j++) {
            int c = lane + 32 * j;
            float zv = v[j] * r * g[c] + b_[c];
            zr[c] = zv;
            zh[c] = __float2half_rn(zv);
        }
    }
}

// ---------------- weight pack + fp16 weight conversion ----------------
__global__ void pack_kernel(const float* __restrict__ off_w, const float* __restrict__ wgt_w,
                            const float* __restrict__ off_b, const float* __restrict__ wgt_b,
                            float* __restrict__ OW, float* __restrict__ OWb)
{
    int i = blockIdx.x * 256 + threadIdx.x;
    if (i < 96 * CC) OW[i] = off_w[i];
    else if (i < 144 * CC) OW[i] = wgt_w[i - 96 * CC];
    else if (i < 144 * CC + 96) OWb[i - 144 * CC] = off_b[i - 144 * CC];
    else if (i < 144 * CC + 144) OWb[i - 144 * CC] = wgt_b[i - 144 * CC - 96];
}

__global__ void w2h_kernel(const float* __restrict__ a, const float* __restrict__ b,
                           const float* __restrict__ c,
                           __half* __restrict__ ah, __half* __restrict__ bh,
                           __half* __restrict__ ch)
{
    int i = blockIdx.x * 256 + threadIdx.x;
    if (i < 256 * 1024) {
        ah[i] = __float2half_rn(a[i]);
        bh[i] = __float2half_rn(b[i]);
        ch[i] = __float2half_rn(c[i]);
    }
}

// ---------------- fused softmax + sampling (per-half, qbase) ----------------
__global__ void __launch_bounds__(256) sample_kernel(
    const float* __restrict__ OFW, const float* __restrict__ sim,
    const __half* __restrict__ V0, const __half* __restrict__ V1,
    const __half* __restrict__ V2, __half* __restrict__ ACC, long long qbase)
{
    __shared__ float sx[96], sy[96], sw[96];
    __shared__ const __half* tptr[96][4];
    __shared__ float twgt[96][4];

    long long q0 = qbase + (long long)blockIdx.x * 2;
    int t = threadIdx.x;

    if (t < 96) {
        int qi = t / 48;
        int pp = t - qi * 48;
        long long q = q0 + qi;
        int nq = (int)(q % NQ);
        int hq = nq >> 6, wq = nq & 63;
        float refx = (wq + 0.5f) * (1.f / 64.f);
        float refy = (hq + 0.5f) * (1.f / 64.f);
        const float* row = OFW + q * 144;
        sx[t] = tanhf(2.f * (refx + row[pp * 2]) - 1.f);
        sy[t] = tanhf(2.f * (refy + row[pp * 2 + 1]) - 1.f);
        sw[t] = row[96 + pp] * (sim[q] + 0.001f);
    }
    __syncthreads();
    if (t < 8) {
        float* w = sw + t * 12;
        float mx = -1e30f;
        #pragma unroll
        for (int p = 0; p < 12; p++) mx = fmaxf(mx, w[p]);
        float sum = 0.f;
        #pragma unroll
        for (int p = 0; p < 12; p++) { w[p] = expf(w[p] - mx); sum += w[p]; }
        float inv = 1.f / sum;
        #pragma unroll
        for (int p = 0; p < 12; p++) w[p] *= inv;
    }
    __syncthreads();
    if (t < 96) {
        int qi = t / 48;
        int pp = t - qi * 48;
        long long q = q0 + qi;
        int bb = (int)(q / NQ);
        int l = (pp % 12) >> 2;
        int sz = 64 >> l;
        const __half* Vb = (l == 0) ? V0 + (size_t)bb * 4096 * CC
                         : (l == 1) ? V1 + (size_t)bb * 1024 * CC
                                    : V2 + (size_t)bb * 256 * CC;
        float x = (sx[t] + 1.f) * 0.5f * (sz - 1);
        float y = (sy[t] + 1.f) * 0.5f * (sz - 1);
        float x0f = floorf(x), y0f = floorf(y);
        int x0 = (int)x0f, y0 = (int)y0f;
        float wx1 = x - x0f, wy1 = y - y0f;
        float w = sw[t];
        float wgs[4] = {(1.f - wy1) * (1.f - wx1), (1.f - wy1) * wx1,
                        wy1 * (1.f - wx1),         wy1 * wx1};
        #pragma unroll
        for (int tap = 0; tap < 4; tap++) {
            int yi = y0 + (tap >> 1), xi = x0 + (tap & 1);
            bool valid = ((unsigned)yi < (unsigned)sz) && ((unsigned)xi < (unsigned)sz);
            int yc = min(max(yi, 0), sz - 1);
            int xc = min(max(xi, 0), sz - 1);
            tptr[t][tap] = Vb + (size_t)(yc * sz + xc) * CC;
            twgt[t][tap] = valid ? w * wgs[tap] : 0.f;
        }
    }
    __syncthreads();

    int warp = t >> 5, lane = t & 31;
    int qi = warp >> 2, h = warp & 3;
    int c8 = lane * 8;

    unsigned long long acc01 = 0, acc23 = 0, acc45 = 0, acc67 = 0;

    #pragma unroll
    for (int i = 0; i < 12; i++) {
        int p = qi * 48 + h * 12 + i;
        #pragma unroll
        for (int tap = 0; tap < 4; tap++) {
            float tw = twgt[p][tap];
            unsigned long long tw2 = pack2(tw, tw);
            const uint4 raw = __ldg((const uint4*)(tptr[p][tap] + c8));
            fma_f32x2(acc01, h2_to_f2u(raw.x), tw2);
            fma_f32x2(acc23, h2_to_f2u(raw.y), tw2);
            fma_f32x2(acc45, h2_to_f2u(raw.z), tw2);
            fma_f32x2(acc67, h2_to_f2u(raw.w), tw2);
        }
    }
    float2 a01 = unpack2(acc01), a23 = unpack2(acc23);
    float2 a45 = unpack2(acc45), a67 = unpack2(acc67);
    __half* out = ACC + (q0 + qi) * 1024 + h * CC + c8;
    uint4 packed;
    packed.x = h2u(__floats2half2_rn(a01.x, a01.y));
    packed.y = h2u(__floats2half2_rn(a23.x, a23.y));
    packed.z = h2u(__floats2half2_rn(a45.x, a45.y));
    packed.w = h2u(__floats2half2_rn(a67.x, a67.y));
    *(uint4*)out = packed;
}

// ---------------- host orchestration (R13 layout) ----------------
struct Streams {
    cudaStream_t s1, s2, s3;
    cudaEvent_t evRoot, ev1, ev2, ev3, evQ, evH1;
    Streams() {
        cudaStreamCreateWithFlags(&s1, cudaStreamNonBlocking);
        cudaStreamCreateWithFlags(&s2, cudaStreamNonBlocking);
        cudaStreamCreateWithFlags(&s3, cudaStreamNonBlocking);
        cudaEventCreateWithFlags(&evRoot, cudaEventDisableTiming);
        cudaEventCreateWithFlags(&ev1, cudaEventDisableTiming);
        cudaEventCreateWithFlags(&ev2, cudaEventDisableTiming);
        cudaEventCreateWithFlags(&ev3, cudaEventDisableTiming);
        cudaEventCreateWithFlags(&evQ, cudaEventDisableTiming);
        cudaEventCreateWithFlags(&evH1, cudaEventDisableTiming);
    }
};

static void gemm_v(cudaStream_t st,
                   const float* A, long long sab, long long sam, long long sak,
                   const float* W, const float* bias,
                   __half* C, long long scb, long long scm,
                   int M, int N, int K, int batch)
{
    dim3 grid(N / BN, M / BM, batch);
    gemm_hc<<<grid, 256, 0, st>>>(A, sab, sam, sak, W, bias,
                                  (float*)C, scb, scm, 1, M, N, K, 1);
}

static void gemm_tail(cudaStream_t st,
                      const __half* A,
                      const __half* W, const float* bias,
                      const float* R, long long srm, long long srn,
                      float* C, long long scm, long long scn,
                      int M, int N, int K, int act, int half_out)
{
    cudaFuncSetAttribute(gemm_hh, cudaFuncAttributeMaxDynamicSharedMemorySize, HH_SMEM);
    dim3 grid(N / BNH, M / BM, 1);
    gemm_hh<<<grid, 256, HH_SMEM, st>>>(A, 0, W, bias, R, 0, srm, srn,
                                        C, 0, scm, scn, M, N, K, act, half_out);
}

static void gemm_prec(cudaStream_t st,
                      const float* A, long long sab, long long sam, long long sak,
                      const float* W, const float* bias,
                      float* C, long long scb, long long scm,
                      int M, int N, int K, int batch)
{
    dim3 grid((N + BN - 1) / BN, M / BM, batch);
    gemm_hc3<<<grid, 256, 0, st>>>(A, sab, sam, sak, W, bias, C, scb, scm, M, N, K);
}

extern "C" void kernel_launch(void* const* d_in, const int* in_sizes, int n_in,
                              void* d_out, int out_size)
{
    static Streams str;

    const float* S     = (const float*)d_in[0];
    const float* f0    = (const float*)d_in[1];
    const float* f1    = (const float*)d_in[2];
    const float* f2    = (const float*)d_in[3];
    const float* sim   = (const float*)d_in[4];
    const float* vw0   = (const float*)d_in[5];
    const float* vb0   = (const float*)d_in[6];
    const float* vw1   = (const float*)d_in[7];
    const float* vb1   = (const float*)d_in[8];
    const float* vw2   = (const float*)d_in[9];
    const float* vb2   = (const float*)d_in[10];
    const float* q_w   = (const float*)d_in[11];
    const float* q_b   = (const float*)d_in[12];
    const float* off_w = (const float*)d_in[13];
    const float* off_b = (const float*)d_in[14];
    const float* wgt_w = (const float*)d_in[15];
    const float* wgt_b = (const float*)d_in[16];
    const float* out_w = (const float*)d_in[17];
    const float* out_b = (const float*)d_in[18];
    const float* lnq_g = (const float*)d_in[19];
    const float* lnq_b = (const float*)d_in[20];
    const float* lno_g = (const float*)d_in[21];
    const float* lno_b = (const float*)d_in[22];
    const float* fc1_w = (const float*)d_in[23];
    const float* fc1_b = (const float*)d_in[24];
    const float* fc2_w = (const float*)d_in[25];
    const float* fc2_b = (const float*)d_in[26];
    float* outp = (float*)d_out;

    float *Q, *OFW, *OW, *OWb, *Y, *Z;
    __half *V0h, *V1h, *V2h, *ACCh, *Zh, *Hh, *OutWh, *F1Wh, *F2Wh;
    cudaGetSymbolAddress((void**)&Q,     g_Q);
    cudaGetSymbolAddress((void**)&V0h,   g_V0h);
    cudaGetSymbolAddress((void**)&V1h,   g_V1h);
    cudaGetSymbolAddress((void**)&V2h,   g_V2h);
    cudaGetSymbolAddress((void**)&OFW,   g_OFW);
    cudaGetSymbolAddress((void**)&OW,    g_OW);
    cudaGetSymbolAddress((void**)&OWb,   g_OWb);
    cudaGetSymbolAddress((void**)&ACCh,  g_ACCh);
    cudaGetSymbolAddress((void**)&Y,     g_Y);
    cudaGetSymbolAddress((void**)&Z,     g_Z);
    cudaGetSymbolAddress((void**)&Zh,    g_Zh);
    cudaGetSymbolAddress((void**)&Hh,    g_Hh);
    cudaGetSymbolAddress((void**)&OutWh, g_OutWh);
    cudaGetSymbolAddress((void**)&F1Wh,  g_F1Wh);
    cudaGetSymbolAddress((void**)&F2Wh,  g_F2Wh);

    cudaStream_t s0 = 0;

    pack_kernel<<<(144 * CC + 144 + 255) / 256, 256, 0, s0>>>(off_w, wgt_w, off_b, wgt_b, OW, OWb);

    cudaEventRecord(str.evRoot, s0);
    cudaStreamWaitEvent(str.s1, str.evRoot, 0);
    cudaStreamWaitEvent(str.s2, str.evRoot, 0);
    cudaStreamWaitEvent(str.s3, str.evRoot, 0);

    // fp16 weight conversion + V projections (R13 layout)
    w2h_kernel<<<1024, 256, 0, str.s1>>>(out_w, fc1_w, fc2_w, OutWh, F1Wh, F2Wh);
    gemm_v(str.s1, f0, (long long)256 * 4096, 1, 4096, vw0, vb0,
           V0h, (long long)4096 * CC, CC, 4096, CC, 256, BB);
    gemm_v(str.s2, f1, (long long)512 * 1024, 1, 1024, vw1, vb1,
           V1h, (long long)1024 * CC, CC, 1024, CC, 512, BB);
    gemm_v(str.s3, f2, (long long)1024 * 256, 1, 256, vw2, vb2,
           V2h, (long long)256 * CC, CC, 256, CC, 1024, BB);
    cudaEventRecord(str.ev1, str.s1);
    cudaEventRecord(str.ev2, str.s2);
    cudaEventRecord(str.ev3, str.s3);

    // ---- shared prefix: q projection + LN over both batches ----
    gemm_prec(s0, S, (long long)CC * NQ, 1, NQ, q_w, q_b,
              Q, (long long)NQ * CC, CC, NQ, CC, CC, BB);
    ln_kernel<<<BB * NQ / 8, 256, 0, s0>>>(Q, lnq_g, lnq_b);
    cudaEventRecord(str.evQ, s0);

    // ---- pipelined per-batch chains: half0 on s0, half1 on s3 ----
    cudaStreamWaitEvent(str.s3, str.evQ, 0);

    // half1 chain on s3
    {
        const long long r1 = (long long)NQ;
        gemm_prec(str.s3, Q + r1 * CC, 0, CC, 1, OW, OWb,
                  OFW + r1 * 144, 0, 144, NQ, 144, CC, 1);
        cudaStreamWaitEvent(str.s3, str.ev1, 0);
        cudaStreamWaitEvent(str.s3, str.ev2, 0);
        sample_kernel<<<NQ / 2, 256, 0, str.s3>>>(OFW, sim, V0h, V1h, V2h, ACCh, r1);
        gemm_tail(str.s3, ACCh + r1 * 1024, OutWh, out_b, nullptr, 0, 0,
                  Y + r1 * CC, CC, 1, NQ, CC, 1024, 0, 0);
        add_ln_kernel<<<NQ / 32, 256, 0, str.s3>>>(S, Y, Z, Zh, lno_g, lno_b, 1);
        gemm_tail(str.s3, Zh + r1 * CC, F1Wh, fc1_b, nullptr, 0, 0,
                  (float*)(Hh + r1 * 1024), 1024, 1, NQ, 1024, CC, 1, 1);
        gemm_tail(str.s3, Hh + r1 * 1024, F2Wh, fc2_b,
                  Z + r1 * CC, CC, 1,
                  outp + (long long)CC * NQ, 1, NQ, NQ, CC, 1024, 0, 0);
        cudaEventRecord(str.evH1, str.s3);
    }

    // half0 chain on s0
    {
        gemm_prec(s0, Q, 0, CC, 1, OW, OWb, OFW, 0, 144, NQ, 144, CC, 1);
        cudaStreamWaitEvent(s0, str.ev1, 0);
        cudaStreamWaitEvent(s0, str.ev2, 0);
        cudaStreamWaitEvent(s0, str.ev3, 0);
        sample_kernel<<<NQ / 2, 256, 0, s0>>>(OFW, sim, V0h, V1h, V2h, ACCh, 0);
        gemm_tail(s0, ACCh, OutWh, out_b, nullptr, 0, 0,
                  Y, CC, 1, NQ, CC, 1024, 0, 0);
        add_ln_kernel<<<NQ / 32, 256, 0, s0>>>(S, Y, Z, Zh, lno_g, lno_b, 0);
        gemm_tail(s0, Zh, F1Wh, fc1_b, nullptr, 0, 0,
                  (float*)Hh, 1024, 1, NQ, 1024, CC, 1, 1);
        gemm_tail(s0, Hh, F2Wh, fc2_b,
                  Z, CC, 1,
                  outp, 1, NQ, NQ, CC, 1024, 0, 0);
    }

    // join
    cudaStreamWaitEvent(s0, str.evH1, 0);
}